// round 2
// baseline (speedup 1.0000x reference)
#include <cuda_runtime.h>
#include <cuda_bf16.h>

#define DIM 64
#define LMAX 200000
#define CMAX 80000

// -------- scratch (static __device__ arrays; no allocation allowed) --------
__device__ float g_Ml2c[(size_t)LMAX * DIM];   // 51.2 MB
__device__ float g_Mc2l[(size_t)CMAX * DIM];   // 20.5 MB
__device__ float g_Ml2l[(size_t)LMAX * DIM];   // 51.2 MB
__device__ float g_aggrC[(size_t)CMAX * DIM];  // 20.5 MB
__device__ float g_aggrL[(size_t)LMAX * DIM];  // 51.2 MB

// ---------------------------------------------------------------------------
// Fused 2-layer MLP: out[r] = relu(x[r] @ W1 + b1) @ W2 + b2
// x is the concat of PARTS row-blocks (each DIM wide). FLIP: read row^1 of x0.
// Tile: 64 rows/block-iter, 256 threads, each thread owns a 4x4 output tile.
// Both operands come from shared via lds.128 -> 16 FMA per 2 LDS.128.
// ---------------------------------------------------------------------------
#define XT_STRIDE 68  // 64 + 4 pad (keeps 16B alignment, breaks bank conflicts)

template <int PARTS, bool FLIP>
__global__ __launch_bounds__(256) void mlp_kernel(
    const float* __restrict__ x0, const float* __restrict__ x1,
    const float* __restrict__ x2,
    const float* __restrict__ W1, const float* __restrict__ b1,
    const float* __restrict__ W2, const float* __restrict__ b2,
    float* __restrict__ out, int nrows)
{
    constexpr int K = PARTS * DIM;
    extern __shared__ float sm[];
    float* W1s = sm;                       // K * 64
    float* W2s = W1s + K * DIM;            // 64 * 64
    float* Xt  = W2s + DIM * DIM;          // K * 68   (transposed: Xt[k][r])
    float* Ht  = Xt + K * XT_STRIDE;       // 64 * 68  (transposed: Ht[k][r])
    float* b1s = Ht + DIM * XT_STRIDE;     // 64
    float* b2s = b1s + DIM;                // 64

    const int tid = threadIdx.x;
    for (int i = tid; i < K * DIM; i += 256) W1s[i] = W1[i];
    for (int i = tid; i < DIM * DIM; i += 256) W2s[i] = W2[i];
    if (tid < DIM) { b1s[tid] = b1[tid]; b2s[tid] = b2[tid]; }

    const int cq = tid & 15;   // column quad: cols 4*cq .. 4*cq+3
    const int rq = tid >> 4;   // row quad:    rows 4*rq .. 4*rq+3
    const int ntiles = (nrows + 63) >> 6;
    __syncthreads();

    for (int tile = blockIdx.x; tile < ntiles; tile += gridDim.x) {
        const int base = tile << 6;

        // ---- stage X^T into shared (coalesced gmem reads) ----
        #pragma unroll
        for (int p = 0; p < PARTS; ++p) {
            const float* xp = (p == 0) ? x0 : ((p == 1) ? x1 : x2);
            #pragma unroll
            for (int i = 0; i < 16; ++i) {
                int idx = tid + i * 256;
                int r = idx >> 6, k = idx & 63;
                int row = base + r;
                float v = 0.f;
                if (row < nrows) {
                    int srow = FLIP ? (row ^ 1) : row;
                    v = xp[srow * DIM + k];
                }
                Xt[(p * DIM + k) * XT_STRIDE + r] = v;
            }
        }
        __syncthreads();

        // ---- layer 1: H = relu(X @ W1 + b1) ----
        float acc[4][4];
        #pragma unroll
        for (int c = 0; c < 4; ++c) {
            float bv = b1s[cq * 4 + c];
            acc[0][c] = bv; acc[1][c] = bv; acc[2][c] = bv; acc[3][c] = bv;
        }
        #pragma unroll 4
        for (int k = 0; k < K; ++k) {
            const float4 xv = *(const float4*)(Xt + k * XT_STRIDE + (rq << 2));
            const float4 wv = *(const float4*)(W1s + (k << 6) + (cq << 2));
            acc[0][0] += xv.x * wv.x; acc[0][1] += xv.x * wv.y; acc[0][2] += xv.x * wv.z; acc[0][3] += xv.x * wv.w;
            acc[1][0] += xv.y * wv.x; acc[1][1] += xv.y * wv.y; acc[1][2] += xv.y * wv.z; acc[1][3] += xv.y * wv.w;
            acc[2][0] += xv.z * wv.x; acc[2][1] += xv.z * wv.y; acc[2][2] += xv.z * wv.z; acc[2][3] += xv.z * wv.w;
            acc[3][0] += xv.w * wv.x; acc[3][1] += xv.w * wv.y; acc[3][2] += xv.w * wv.z; acc[3][3] += xv.w * wv.w;
        }
        // relu + store H transposed
        #pragma unroll
        for (int c = 0; c < 4; ++c) {
            float4 h;
            h.x = fmaxf(acc[0][c], 0.f); h.y = fmaxf(acc[1][c], 0.f);
            h.z = fmaxf(acc[2][c], 0.f); h.w = fmaxf(acc[3][c], 0.f);
            *(float4*)(Ht + (cq * 4 + c) * XT_STRIDE + (rq << 2)) = h;
        }
        __syncthreads();

        // ---- layer 2: out = H @ W2 + b2 ----
        float o[4][4];
        #pragma unroll
        for (int c = 0; c < 4; ++c) {
            float bv = b2s[cq * 4 + c];
            o[0][c] = bv; o[1][c] = bv; o[2][c] = bv; o[3][c] = bv;
        }
        #pragma unroll 4
        for (int k = 0; k < DIM; ++k) {
            const float4 xv = *(const float4*)(Ht + k * XT_STRIDE + (rq << 2));
            const float4 wv = *(const float4*)(W2s + (k << 6) + (cq << 2));
            o[0][0] += xv.x * wv.x; o[0][1] += xv.x * wv.y; o[0][2] += xv.x * wv.z; o[0][3] += xv.x * wv.w;
            o[1][0] += xv.y * wv.x; o[1][1] += xv.y * wv.y; o[1][2] += xv.y * wv.z; o[1][3] += xv.y * wv.w;
            o[2][0] += xv.z * wv.x; o[2][1] += xv.z * wv.y; o[2][2] += xv.z * wv.z; o[2][3] += xv.z * wv.w;
            o[3][0] += xv.w * wv.x; o[3][1] += xv.w * wv.y; o[3][2] += xv.w * wv.z; o[3][3] += xv.w * wv.w;
        }
        #pragma unroll
        for (int r = 0; r < 4; ++r) {
            int row = base + (rq << 2) + r;
            if (row < nrows)
                *(float4*)(out + (size_t)row * DIM + (cq << 2)) =
                    make_float4(o[r][0], o[r][1], o[r][2], o[r][3]);
        }
        __syncthreads();
    }
}

// ---------------------------------------------------------------------------
// Edge scatter-add: dst[didx[e]] += src[sidx[e]]   (64 floats / edge)
// 16 threads per edge, float4 atomics (sm_90+ native vector atomicAdd).
// ---------------------------------------------------------------------------
__global__ __launch_bounds__(256) void scatter_kernel(
    const float* __restrict__ src, const int* __restrict__ sidx,
    const int* __restrict__ didx, float* __restrict__ dst, int E)
{
    __shared__ int ss[16], sd[16];
    const int e0 = blockIdx.x * 16;
    if (threadIdx.x < 16) {
        int e = e0 + threadIdx.x;
        ss[threadIdx.x] = (e < E) ? sidx[e] : 0;
    } else if (threadIdx.x < 32) {
        int e = e0 + threadIdx.x - 16;
        sd[threadIdx.x - 16] = (e < E) ? didx[e] : 0;
    }
    __syncthreads();
    const int le = threadIdx.x >> 4;
    const int q  = threadIdx.x & 15;
    if (e0 + le < E) {
        const int s = ss[le], d = sd[le];
        float4 v = *(const float4*)(src + (size_t)s * DIM + q * 4);
#if CUDART_VERSION >= 12030
        atomicAdd(((float4*)(dst + (size_t)d * DIM)) + q, v);
#else
        float* p = dst + (size_t)d * DIM + q * 4;
        atomicAdd(p + 0, v.x); atomicAdd(p + 1, v.y);
        atomicAdd(p + 2, v.z); atomicAdd(p + 3, v.w);
#endif
    }
}

// ---------------------------------------------------------------------------
static inline size_t mlp_smem_bytes(int parts)
{
    int K = parts * DIM;
    return (size_t)(K * DIM + DIM * DIM + K * XT_STRIDE + DIM * XT_STRIDE + 2 * DIM)
           * sizeof(float);
}

extern "C" void kernel_launch(void* const* d_in, const int* in_sizes, int n_in,
                              void* d_out, int out_size)
{
    // Input order: [l_size, c_size,] l_edge, c_edge, l_emb, c_emb, then 5 MLPs x4.
    const int off = n_in - 24;  // 2 if scalar sizes are present, else 0
    const int* l_edge = (const int*)d_in[off + 0];
    const int* c_edge = (const int*)d_in[off + 1];
    const float* l_emb_in = (const float*)d_in[off + 2];
    const float* c_emb_in = (const float*)d_in[off + 3];
    const int E = in_sizes[off + 0];
    const int L = in_sizes[off + 2] / DIM;
    const int C = in_sizes[off + 3] / DIM;

    const float* W[5][4];
    for (int m = 0; m < 5; ++m)
        for (int j = 0; j < 4; ++j)
            W[m][j] = (const float*)d_in[off + 4 + m * 4 + j];
    // m: 0=l2c, 1=c2l, 2=l2l, 3=cu, 4=lu

    float* Ml2c, * Mc2l, * Ml2l, * aggrC, * aggrL;
    cudaGetSymbolAddress((void**)&Ml2c, g_Ml2c);
    cudaGetSymbolAddress((void**)&Mc2l, g_Mc2l);
    cudaGetSymbolAddress((void**)&Ml2l, g_Ml2l);
    cudaGetSymbolAddress((void**)&aggrC, g_aggrC);
    cudaGetSymbolAddress((void**)&aggrL, g_aggrL);

    const size_t sm1 = mlp_smem_bytes(1), sm2 = mlp_smem_bytes(2), sm3 = mlp_smem_bytes(3);
    cudaFuncSetAttribute(mlp_kernel<1, false>, cudaFuncAttributeMaxDynamicSharedMemorySize, (int)sm1);
    cudaFuncSetAttribute(mlp_kernel<1, true>,  cudaFuncAttributeMaxDynamicSharedMemorySize, (int)sm1);
    cudaFuncSetAttribute(mlp_kernel<2, false>, cudaFuncAttributeMaxDynamicSharedMemorySize, (int)sm2);
    cudaFuncSetAttribute(mlp_kernel<3, false>, cudaFuncAttributeMaxDynamicSharedMemorySize, (int)sm3);

    float* outBase = (float*)d_out;
    float* outL = outBase;                          // (3, L, 64)
    float* outC = outBase + (size_t)3 * L * DIM;    // (3, C, 64)

    // slot 0 = input embeddings
    cudaMemcpyAsync(outL, l_emb_in, (size_t)L * DIM * sizeof(float), cudaMemcpyDeviceToDevice);
    cudaMemcpyAsync(outC, c_emb_in, (size_t)C * DIM * sizeof(float), cudaMemcpyDeviceToDevice);

    const int ltiles = (L + 63) >> 6;
    const int ctiles = (C + 63) >> 6;
    auto gridFor = [](int tiles, int maxResident) {
        return tiles < maxResident ? tiles : maxResident;
    };
    const int g1L = gridFor(ltiles, 444);  // parts=1 (~68KB smem -> 3 blocks/SM)
    const int g1C = gridFor(ctiles, 444);
    const int g2C = gridFor(ctiles, 296);  // parts=2 (~102KB -> 2 blocks/SM)
    const int g3L = gridFor(ltiles, 148);  // parts=3 (~136KB -> 1 block/SM)
    const int scatterBlocks = (E + 15) / 16;

    for (int t = 0; t < 2; ++t) {
        const float* le = outL + (size_t)t * L * DIM;
        const float* ce = outC + (size_t)t * C * DIM;
        float* nle = outL + (size_t)(t + 1) * L * DIM;
        float* nce = outC + (size_t)(t + 1) * C * DIM;

        cudaMemsetAsync(aggrC, 0, (size_t)C * DIM * sizeof(float));
        cudaMemsetAsync(aggrL, 0, (size_t)L * DIM * sizeof(float));

        // messages (from OLD embeddings)
        mlp_kernel<1, false><<<g1L, 256, sm1>>>(le, nullptr, nullptr,
            W[0][0], W[0][1], W[0][2], W[0][3], Ml2c, L);
        mlp_kernel<1, false><<<g1C, 256, sm1>>>(ce, nullptr, nullptr,
            W[1][0], W[1][1], W[1][2], W[1][3], Mc2l, C);
        mlp_kernel<1, true><<<g1L, 256, sm1>>>(le, nullptr, nullptr,
            W[2][0], W[2][1], W[2][2], W[2][3], Ml2l, L);

        // aggregation: aggrC[c_edge[e]] += Ml2c[l_edge[e]];  aggrL[l_edge[e]] += Mc2l[c_edge[e]]
        scatter_kernel<<<scatterBlocks, 256>>>(Ml2c, l_edge, c_edge, aggrC, E);
        scatter_kernel<<<scatterBlocks, 256>>>(Mc2l, c_edge, l_edge, aggrL, E);

        // updates
        mlp_kernel<2, false><<<g2C, 256, sm2>>>(ce, aggrC, nullptr,
            W[3][0], W[3][1], W[3][2], W[3][3], nce, C);
        mlp_kernel<3, false><<<g3L, 256, sm3>>>(le, aggrL, Ml2l,
            W[4][0], W[4][1], W[4][2], W[4][3], nle, L);
    }
    (void)out_size;
}

// round 6
// speedup vs baseline: 1.8483x; 1.8483x over previous
#include <cuda_runtime.h>
#include <cuda_fp16.h>
#include <cstdint>

#define DIM 64
#define LMAX 200000
#define CMAX 80000

// -------- scratch (static __device__ arrays; no allocation allowed) --------
__device__ float g_Ml2c[(size_t)LMAX * DIM];   // 51.2 MB
__device__ float g_Mc2l[(size_t)CMAX * DIM];   // 20.5 MB
__device__ float g_Ml2l[(size_t)LMAX * DIM];   // 51.2 MB
__device__ float g_aggrC[(size_t)CMAX * DIM];  // 20.5 MB
__device__ float g_aggrL[(size_t)LMAX * DIM];  // 51.2 MB

// ---------------------------------------------------------------------------
__device__ __forceinline__ void mma_16816(float* d, const uint32_t* a,
                                          const uint32_t* b)
{
    asm volatile(
        "mma.sync.aligned.m16n8k16.row.col.f32.f16.f16.f32 "
        "{%0,%1,%2,%3}, {%4,%5,%6,%7}, {%8,%9}, {%0,%1,%2,%3};\n"
        : "+f"(d[0]), "+f"(d[1]), "+f"(d[2]), "+f"(d[3])
        : "r"(a[0]), "r"(a[1]), "r"(a[2]), "r"(a[3]), "r"(b[0]), "r"(b[1]));
}

// split a float pair into (hi, lo) fp16 pairs: x ~= hi + lo
__device__ __forceinline__ void split2(float x, float y, __half2& hi, __half2& lo)
{
    hi = __floats2half2_rn(x, y);
    float2 hf = __half22float2(hi);
    lo = __floats2half2_rn(x - hf.x, y - hf.y);
}

// ---------------------------------------------------------------------------
// fp16-split tensor-core fused 2-layer MLP: out = relu(X@W1+b1)@W2+b2
// Each operand is hi+lo fp16; GEMM = hi*hi + hi*lo + lo*hi, fp32 accumulate
// (~2^-21 per-op error). X = concat of PARTS 64-wide row-blocks.
// FLIPOUT: result of row r written to row r^1 (tiles are 64-aligned).
// Block: 128 threads = 4 warps; 64x64 output tile; warp = 32x32 quadrant of
// m16n8k16 MMAs. All fragment LDS are bank-conflict-free by stride choice.
// ---------------------------------------------------------------------------
template <int PARTS, bool FLIPOUT>
__global__ __launch_bounds__(128) void mlp_tc(
    const float* __restrict__ x0, const float* __restrict__ x1,
    const float* __restrict__ x2,
    const float* __restrict__ W1, const float* __restrict__ b1,
    const float* __restrict__ W2, const float* __restrict__ b2,
    float* __restrict__ out, int nrows)
{
    constexpr int K  = PARTS * 64;
    constexpr int WS = K + 8;   // W1 row stride in halves (word-stride == 4 mod 32)
    constexpr int XS = 72;      // X/H/W2 row stride in halves

    extern __shared__ __half smh[];
    __half* W1h = smh;                 // [64][WS]  (n-major: W1h[n][k])
    __half* W1l = W1h + 64 * WS;
    __half* W2h = W1l + 64 * WS;       // [64][XS]
    __half* W2l = W2h + 64 * XS;
    __half* Xh  = W2l + 64 * XS;       // [64][XS]  one 64-col chunk of X
    __half* Xl  = Xh + 64 * XS;
    __half* Hh  = Xl + 64 * XS;        // [64][XS]
    __half* Hl  = Hh + 64 * XS;
    float*  b1s = (float*)(Hl + 64 * XS);
    float*  b2s = b1s + 64;

    const int tid = threadIdx.x;
    // stage weights transposed (n-major), hi/lo split
    for (int i = tid; i < K * 64; i += 128) {
        int k = i >> 6, n = i & 63;
        float w = W1[i];
        __half hi = __float2half_rn(w);
        W1h[n * WS + k] = hi;
        W1l[n * WS + k] = __float2half_rn(w - __half2float(hi));
    }
    for (int i = tid; i < 64 * 64; i += 128) {
        int k = i >> 6, n = i & 63;
        float w = W2[i];
        __half hi = __float2half_rn(w);
        W2h[n * XS + k] = hi;
        W2l[n * XS + k] = __float2half_rn(w - __half2float(hi));
    }
    if (tid < 64) { b1s[tid] = b1[tid]; b2s[tid] = b2[tid]; }
    __syncthreads();   // REQUIRED: acc-init below reads b1s/b2s across warps
                       // (missing barrier here was the R3/R4 correctness bug)

    const int lane = tid & 31;
    const int warp = tid >> 5;
    const int gid = lane >> 2, tig = lane & 3;
    const int wm = (warp & 1) * 32;    // warp row offset in 64x64 tile
    const int wn = (warp >> 1) * 32;   // warp col offset

    const int ntiles = (nrows + 63) >> 6;
    for (int tile = blockIdx.x; tile < ntiles; tile += gridDim.x) {
        const int base = tile << 6;

        // ---- layer-1 accumulators, init with bias (exact fp32) ----
        float acc[2][4][4];
        #pragma unroll
        for (int nt = 0; nt < 4; ++nt) {
            float bv0 = b1s[wn + nt * 8 + 2 * tig];
            float bv1 = b1s[wn + nt * 8 + 2 * tig + 1];
            #pragma unroll
            for (int mt = 0; mt < 2; ++mt) {
                acc[mt][nt][0] = bv0; acc[mt][nt][1] = bv1;
                acc[mt][nt][2] = bv0; acc[mt][nt][3] = bv1;
            }
        }

        #pragma unroll
        for (int p = 0; p < PARTS; ++p) {
            const float* xp = (p == 0) ? x0 : ((p == 1) ? x1 : x2);
            __syncthreads();   // Xs free for reuse (prev part / prev tile done)
            #pragma unroll
            for (int i = 0; i < 16; ++i) {
                int idx = tid + i * 128;       // 2048 half2-pairs
                int r = idx >> 5, kp = idx & 31;
                int row = base + r;
                float2 v = make_float2(0.f, 0.f);
                if (row < nrows) v = *(const float2*)(xp + (size_t)row * 64 + 2 * kp);
                __half2 hi, lo;
                split2(v.x, v.y, hi, lo);
                *(__half2*)(Xh + r * XS + 2 * kp) = hi;
                *(__half2*)(Xl + r * XS + 2 * kp) = lo;
            }
            __syncthreads();

            #pragma unroll
            for (int kb = 0; kb < 4; ++kb) {
                const int k0 = kb * 16;
                uint32_t ah[2][4], al[2][4];
                #pragma unroll
                for (int mt = 0; mt < 2; ++mt) {
                    int r0 = (wm + mt * 16 + gid) * XS;
                    int r8 = r0 + 8 * XS;
                    ah[mt][0] = *(const uint32_t*)(Xh + r0 + k0 + 2 * tig);
                    ah[mt][1] = *(const uint32_t*)(Xh + r8 + k0 + 2 * tig);
                    ah[mt][2] = *(const uint32_t*)(Xh + r0 + k0 + 2 * tig + 8);
                    ah[mt][3] = *(const uint32_t*)(Xh + r8 + k0 + 2 * tig + 8);
                    al[mt][0] = *(const uint32_t*)(Xl + r0 + k0 + 2 * tig);
                    al[mt][1] = *(const uint32_t*)(Xl + r8 + k0 + 2 * tig);
                    al[mt][2] = *(const uint32_t*)(Xl + r0 + k0 + 2 * tig + 8);
                    al[mt][3] = *(const uint32_t*)(Xl + r8 + k0 + 2 * tig + 8);
                }
                const int kk = p * 64 + k0;
                uint32_t bh[4][2], bl[4][2];
                #pragma unroll
                for (int nt = 0; nt < 4; ++nt) {
                    int n = (wn + nt * 8 + gid) * WS;
                    bh[nt][0] = *(const uint32_t*)(W1h + n + kk + 2 * tig);
                    bh[nt][1] = *(const uint32_t*)(W1h + n + kk + 2 * tig + 8);
                    bl[nt][0] = *(const uint32_t*)(W1l + n + kk + 2 * tig);
                    bl[nt][1] = *(const uint32_t*)(W1l + n + kk + 2 * tig + 8);
                }
                #pragma unroll
                for (int nt = 0; nt < 4; ++nt) {
                    mma_16816(acc[0][nt], ah[0], bh[nt]);
                    mma_16816(acc[1][nt], ah[1], bh[nt]);
                }
                #pragma unroll
                for (int nt = 0; nt < 4; ++nt) {
                    mma_16816(acc[0][nt], ah[0], bl[nt]);
                    mma_16816(acc[1][nt], ah[1], bl[nt]);
                }
                #pragma unroll
                for (int nt = 0; nt < 4; ++nt) {
                    mma_16816(acc[0][nt], al[0], bh[nt]);
                    mma_16816(acc[1][nt], al[1], bh[nt]);
                }
            }
        }

        // ---- relu -> H (hi/lo split) ----
        #pragma unroll
        for (int mt = 0; mt < 2; ++mt)
            #pragma unroll
            for (int nt = 0; nt < 4; ++nt) {
                int r0 = wm + mt * 16 + gid;
                int c0 = wn + nt * 8 + 2 * tig;
                float v0 = fmaxf(acc[mt][nt][0], 0.f);
                float v1 = fmaxf(acc[mt][nt][1], 0.f);
                float v2 = fmaxf(acc[mt][nt][2], 0.f);
                float v3 = fmaxf(acc[mt][nt][3], 0.f);
                __half2 hi, lo;
                split2(v0, v1, hi, lo);
                *(__half2*)(Hh + r0 * XS + c0) = hi;
                *(__half2*)(Hl + r0 * XS + c0) = lo;
                split2(v2, v3, hi, lo);
                *(__half2*)(Hh + (r0 + 8) * XS + c0) = hi;
                *(__half2*)(Hl + (r0 + 8) * XS + c0) = lo;
            }
        __syncthreads();

        // ---- layer 2 ----
        float o[2][4][4];
        #pragma unroll
        for (int nt = 0; nt < 4; ++nt) {
            float bv0 = b2s[wn + nt * 8 + 2 * tig];
            float bv1 = b2s[wn + nt * 8 + 2 * tig + 1];
            #pragma unroll
            for (int mt = 0; mt < 2; ++mt) {
                o[mt][nt][0] = bv0; o[mt][nt][1] = bv1;
                o[mt][nt][2] = bv0; o[mt][nt][3] = bv1;
            }
        }
        #pragma unroll
        for (int kb = 0; kb < 4; ++kb) {
            const int k0 = kb * 16;
            uint32_t ah[2][4], al[2][4];
            #pragma unroll
            for (int mt = 0; mt < 2; ++mt) {
                int r0 = (wm + mt * 16 + gid) * XS;
                int r8 = r0 + 8 * XS;
                ah[mt][0] = *(const uint32_t*)(Hh + r0 + k0 + 2 * tig);
                ah[mt][1] = *(const uint32_t*)(Hh + r8 + k0 + 2 * tig);
                ah[mt][2] = *(const uint32_t*)(Hh + r0 + k0 + 2 * tig + 8);
                ah[mt][3] = *(const uint32_t*)(Hh + r8 + k0 + 2 * tig + 8);
                al[mt][0] = *(const uint32_t*)(Hl + r0 + k0 + 2 * tig);
                al[mt][1] = *(const uint32_t*)(Hl + r8 + k0 + 2 * tig);
                al[mt][2] = *(const uint32_t*)(Hl + r0 + k0 + 2 * tig + 8);
                al[mt][3] = *(const uint32_t*)(Hl + r8 + k0 + 2 * tig + 8);
            }
            uint32_t bh[4][2], bl[4][2];
            #pragma unroll
            for (int nt = 0; nt < 4; ++nt) {
                int n = (wn + nt * 8 + gid) * XS;
                bh[nt][0] = *(const uint32_t*)(W2h + n + k0 + 2 * tig);
                bh[nt][1] = *(const uint32_t*)(W2h + n + k0 + 2 * tig + 8);
                bl[nt][0] = *(const uint32_t*)(W2l + n + k0 + 2 * tig);
                bl[nt][1] = *(const uint32_t*)(W2l + n + k0 + 2 * tig + 8);
            }
            #pragma unroll
            for (int nt = 0; nt < 4; ++nt) {
                mma_16816(o[0][nt], ah[0], bh[nt]);
                mma_16816(o[1][nt], ah[1], bh[nt]);
            }
            #pragma unroll
            for (int nt = 0; nt < 4; ++nt) {
                mma_16816(o[0][nt], ah[0], bl[nt]);
                mma_16816(o[1][nt], ah[1], bl[nt]);
            }
            #pragma unroll
            for (int nt = 0; nt < 4; ++nt) {
                mma_16816(o[0][nt], al[0], bh[nt]);
                mma_16816(o[1][nt], al[1], bh[nt]);
            }
        }

        // ---- epilogue: float2 stores (FLIPOUT writes row r^1) ----
        #pragma unroll
        for (int mt = 0; mt < 2; ++mt)
            #pragma unroll
            for (int nt = 0; nt < 4; ++nt) {
                int r = base + wm + mt * 16 + gid;
                int c = wn + nt * 8 + 2 * tig;
                if (r < nrows) {
                    int ro = FLIPOUT ? (r ^ 1) : r;
                    *(float2*)(out + (size_t)ro * 64 + c) =
                        make_float2(o[mt][nt][0], o[mt][nt][1]);
                }
                if (r + 8 < nrows) {
                    int ro = FLIPOUT ? ((r + 8) ^ 1) : (r + 8);
                    *(float2*)(out + (size_t)ro * 64 + c) =
                        make_float2(o[mt][nt][2], o[mt][nt][3]);
                }
            }
        // next iteration's first __syncthreads() protects Xs/Hs reuse
    }
}

// ---------------------------------------------------------------------------
// Edge scatter-add: dst[didx[e]] += src[sidx[e]]   (64 floats / edge)
// 16 threads per edge, float4 atomics.
// ---------------------------------------------------------------------------
__global__ __launch_bounds__(256) void scatter_kernel(
    const float* __restrict__ src, const int* __restrict__ sidx,
    const int* __restrict__ didx, float* __restrict__ dst, int E)
{
    __shared__ int ss[16], sd[16];
    const int e0 = blockIdx.x * 16;
    if (threadIdx.x < 16) {
        int e = e0 + threadIdx.x;
        ss[threadIdx.x] = (e < E) ? sidx[e] : 0;
    } else if (threadIdx.x < 32) {
        int e = e0 + threadIdx.x - 16;
        sd[threadIdx.x - 16] = (e < E) ? didx[e] : 0;
    }
    __syncthreads();
    const int le = threadIdx.x >> 4;
    const int q  = threadIdx.x & 15;
    if (e0 + le < E) {
        const int s = ss[le], d = sd[le];
        float4 v = *(const float4*)(src + (size_t)s * DIM + q * 4);
#if CUDART_VERSION >= 12030
        atomicAdd(((float4*)(dst + (size_t)d * DIM)) + q, v);
#else
        float* p = dst + (size_t)d * DIM + q * 4;
        atomicAdd(p + 0, v.x); atomicAdd(p + 1, v.y);
        atomicAdd(p + 2, v.z); atomicAdd(p + 3, v.w);
#endif
    }
}

// ---------------------------------------------------------------------------
static inline size_t mlp_smem_bytes(int parts)
{
    int WS = parts * 64 + 8;
    size_t halves = (size_t)2 * 64 * WS + (size_t)6 * 64 * 72;
    return halves * 2 + 128 * sizeof(float);
}

extern "C" void kernel_launch(void* const* d_in, const int* in_sizes, int n_in,
                              void* d_out, int out_size)
{
    // Input order: [l_size, c_size,] l_edge, c_edge, l_emb, c_emb, then 5 MLPs x4.
    const int off = n_in - 24;
    const int* l_edge = (const int*)d_in[off + 0];
    const int* c_edge = (const int*)d_in[off + 1];
    const float* l_emb_in = (const float*)d_in[off + 2];
    const float* c_emb_in = (const float*)d_in[off + 3];
    const int E = in_sizes[off + 0];
    const int L = in_sizes[off + 2] / DIM;
    const int C = in_sizes[off + 3] / DIM;

    const float* W[5][4];
    for (int m = 0; m < 5; ++m)
        for (int j = 0; j < 4; ++j)
            W[m][j] = (const float*)d_in[off + 4 + m * 4 + j];
    // m: 0=l2c, 1=c2l, 2=l2l, 3=cu, 4=lu

    float* Ml2c, * Mc2l, * Ml2l, * aggrC, * aggrL;
    cudaGetSymbolAddress((void**)&Ml2c, g_Ml2c);
    cudaGetSymbolAddress((void**)&Mc2l, g_Mc2l);
    cudaGetSymbolAddress((void**)&Ml2l, g_Ml2l);
    cudaGetSymbolAddress((void**)&aggrC, g_aggrC);
    cudaGetSymbolAddress((void**)&aggrL, g_aggrL);

    const size_t sm1 = mlp_smem_bytes(1);
    const size_t sm2 = mlp_smem_bytes(2);
    const size_t sm3 = mlp_smem_bytes(3);
    cudaFuncSetAttribute(mlp_tc<1, false>, cudaFuncAttributeMaxDynamicSharedMemorySize, (int)sm1);
    cudaFuncSetAttribute(mlp_tc<1, true>,  cudaFuncAttributeMaxDynamicSharedMemorySize, (int)sm1);
    cudaFuncSetAttribute(mlp_tc<2, false>, cudaFuncAttributeMaxDynamicSharedMemorySize, (int)sm2);
    cudaFuncSetAttribute(mlp_tc<3, false>, cudaFuncAttributeMaxDynamicSharedMemorySize, (int)sm3);

    float* outBase = (float*)d_out;
    float* outL = outBase;                          // (3, L, 64)
    float* outC = outBase + (size_t)3 * L * DIM;    // (3, C, 64)

    cudaMemcpyAsync(outL, l_emb_in, (size_t)L * DIM * sizeof(float), cudaMemcpyDeviceToDevice);
    cudaMemcpyAsync(outC, c_emb_in, (size_t)C * DIM * sizeof(float), cudaMemcpyDeviceToDevice);

    const int ltiles = (L + 63) >> 6;
    const int ctiles = (C + 63) >> 6;
    auto gridFor = [](int tiles, int maxResident) {
        return tiles < maxResident ? tiles : maxResident;
    };
    const int g1L = gridFor(ltiles, 148 * 3);   // parts=1: ~72.5KB smem -> 3 blocks/SM
    const int g1C = gridFor(ctiles, 148 * 3);
    const int g2C = gridFor(ctiles, 148 * 2);   // parts=2: ~88.5KB -> 2 blocks/SM
    const int g3L = gridFor(ltiles, 148 * 2);   // parts=3: ~104.5KB -> 2 blocks/SM
    const int scatterBlocks = (E + 15) / 16;

    for (int t = 0; t < 2; ++t) {
        const float* le = outL + (size_t)t * L * DIM;
        const float* ce = outC + (size_t)t * C * DIM;
        float* nle = outL + (size_t)(t + 1) * L * DIM;
        float* nce = outC + (size_t)(t + 1) * C * DIM;

        cudaMemsetAsync(aggrC, 0, (size_t)C * DIM * sizeof(float));
        cudaMemsetAsync(aggrL, 0, (size_t)L * DIM * sizeof(float));

        // messages (from OLD embeddings)
        mlp_tc<1, false><<<g1L, 128, sm1>>>(le, nullptr, nullptr,
            W[0][0], W[0][1], W[0][2], W[0][3], Ml2c, L);
        mlp_tc<1, false><<<g1C, 128, sm1>>>(ce, nullptr, nullptr,
            W[1][0], W[1][1], W[1][2], W[1][3], Mc2l, C);
        mlp_tc<1, true><<<g1L, 128, sm1>>>(le, nullptr, nullptr,
            W[2][0], W[2][1], W[2][2], W[2][3], Ml2l, L);

        // aggregation
        scatter_kernel<<<scatterBlocks, 256>>>(Ml2c, l_edge, c_edge, aggrC, E);
        scatter_kernel<<<scatterBlocks, 256>>>(Mc2l, c_edge, l_edge, aggrL, E);

        // updates
        mlp_tc<2, false><<<g2C, 128, sm2>>>(ce, aggrC, nullptr,
            W[3][0], W[3][1], W[3][2], W[3][3], nce, C);
        mlp_tc<3, false><<<g3L, 128, sm3>>>(le, aggrL, Ml2l,
            W[4][0], W[4][1], W[4][2], W[4][3], nle, L);
    }
    (void)out_size;
}

// round 7
// speedup vs baseline: 2.3889x; 1.2925x over previous
#include <cuda_runtime.h>
#include <cuda_fp16.h>
#include <cstdint>

#define DIM 64
#define LMAX 200000
#define CMAX 80000
#define EMAX 1100000
#define SCAN_NB 256

// -------- scratch (static __device__ arrays; no allocation allowed) --------
__device__ float g_Ml2c[(size_t)LMAX * DIM];   // 51.2 MB
__device__ float g_Mc2l[(size_t)CMAX * DIM];   // 20.5 MB
__device__ float g_Ml2l[(size_t)LMAX * DIM];   // 51.2 MB
__device__ float g_aggrC[(size_t)CMAX * DIM];  // 20.5 MB
__device__ float g_aggrL[(size_t)LMAX * DIM];  // 51.2 MB
// CSR scratch
__device__ int g_cntC[CMAX],  g_rowC[CMAX + 1], g_curC[CMAX], g_srcC[EMAX];
__device__ int g_cntL[LMAX],  g_rowL[LMAX + 1], g_curL[LMAX], g_srcL[EMAX];
__device__ int g_bsumC[SCAN_NB], g_bsumL[SCAN_NB];

// ---------------------------------------------------------------------------
__device__ __forceinline__ void mma_16816(float* d, const uint32_t* a,
                                          const uint32_t* b)
{
    asm volatile(
        "mma.sync.aligned.m16n8k16.row.col.f32.f16.f16.f32 "
        "{%0,%1,%2,%3}, {%4,%5,%6,%7}, {%8,%9}, {%0,%1,%2,%3};\n"
        : "+f"(d[0]), "+f"(d[1]), "+f"(d[2]), "+f"(d[3])
        : "r"(a[0]), "r"(a[1]), "r"(a[2]), "r"(a[3]), "r"(b[0]), "r"(b[1]));
}

__device__ __forceinline__ void split2(float x, float y, __half2& hi, __half2& lo)
{
    hi = __floats2half2_rn(x, y);
    float2 hf = __half22float2(hi);
    lo = __floats2half2_rn(x - hf.x, y - hf.y);
}

// ---------------------------------------------------------------------------
// fp16-split tensor-core fused 2-layer MLP (validated in R6).
// ---------------------------------------------------------------------------
template <int PARTS, bool FLIPOUT>
__global__ __launch_bounds__(128) void mlp_tc(
    const float* __restrict__ x0, const float* __restrict__ x1,
    const float* __restrict__ x2,
    const float* __restrict__ W1, const float* __restrict__ b1,
    const float* __restrict__ W2, const float* __restrict__ b2,
    float* __restrict__ out, int nrows)
{
    constexpr int K  = PARTS * 64;
    constexpr int WS = K + 8;
    constexpr int XS = 72;

    extern __shared__ __half smh[];
    __half* W1h = smh;
    __half* W1l = W1h + 64 * WS;
    __half* W2h = W1l + 64 * WS;
    __half* W2l = W2h + 64 * XS;
    __half* Xh  = W2l + 64 * XS;
    __half* Xl  = Xh + 64 * XS;
    __half* Hh  = Xl + 64 * XS;
    __half* Hl  = Hh + 64 * XS;
    float*  b1s = (float*)(Hl + 64 * XS);
    float*  b2s = b1s + 64;

    const int tid = threadIdx.x;
    for (int i = tid; i < K * 64; i += 128) {
        int k = i >> 6, n = i & 63;
        float w = W1[i];
        __half hi = __float2half_rn(w);
        W1h[n * WS + k] = hi;
        W1l[n * WS + k] = __float2half_rn(w - __half2float(hi));
    }
    for (int i = tid; i < 64 * 64; i += 128) {
        int k = i >> 6, n = i & 63;
        float w = W2[i];
        __half hi = __float2half_rn(w);
        W2h[n * XS + k] = hi;
        W2l[n * XS + k] = __float2half_rn(w - __half2float(hi));
    }
    if (tid < 64) { b1s[tid] = b1[tid]; b2s[tid] = b2[tid]; }
    __syncthreads();   // REQUIRED: acc-init reads b1s/b2s across warps

    const int lane = tid & 31;
    const int warp = tid >> 5;
    const int gid = lane >> 2, tig = lane & 3;
    const int wm = (warp & 1) * 32;
    const int wn = (warp >> 1) * 32;

    const int ntiles = (nrows + 63) >> 6;
    for (int tile = blockIdx.x; tile < ntiles; tile += gridDim.x) {
        const int base = tile << 6;

        float acc[2][4][4];
        #pragma unroll
        for (int nt = 0; nt < 4; ++nt) {
            float bv0 = b1s[wn + nt * 8 + 2 * tig];
            float bv1 = b1s[wn + nt * 8 + 2 * tig + 1];
            #pragma unroll
            for (int mt = 0; mt < 2; ++mt) {
                acc[mt][nt][0] = bv0; acc[mt][nt][1] = bv1;
                acc[mt][nt][2] = bv0; acc[mt][nt][3] = bv1;
            }
        }

        #pragma unroll
        for (int p = 0; p < PARTS; ++p) {
            const float* xp = (p == 0) ? x0 : ((p == 1) ? x1 : x2);
            __syncthreads();
            #pragma unroll
            for (int i = 0; i < 16; ++i) {
                int idx = tid + i * 128;
                int r = idx >> 5, kp = idx & 31;
                int row = base + r;
                float2 v = make_float2(0.f, 0.f);
                if (row < nrows) v = *(const float2*)(xp + (size_t)row * 64 + 2 * kp);
                __half2 hi, lo;
                split2(v.x, v.y, hi, lo);
                *(__half2*)(Xh + r * XS + 2 * kp) = hi;
                *(__half2*)(Xl + r * XS + 2 * kp) = lo;
            }
            __syncthreads();

            #pragma unroll
            for (int kb = 0; kb < 4; ++kb) {
                const int k0 = kb * 16;
                uint32_t ah[2][4], al[2][4];
                #pragma unroll
                for (int mt = 0; mt < 2; ++mt) {
                    int r0 = (wm + mt * 16 + gid) * XS;
                    int r8 = r0 + 8 * XS;
                    ah[mt][0] = *(const uint32_t*)(Xh + r0 + k0 + 2 * tig);
                    ah[mt][1] = *(const uint32_t*)(Xh + r8 + k0 + 2 * tig);
                    ah[mt][2] = *(const uint32_t*)(Xh + r0 + k0 + 2 * tig + 8);
                    ah[mt][3] = *(const uint32_t*)(Xh + r8 + k0 + 2 * tig + 8);
                    al[mt][0] = *(const uint32_t*)(Xl + r0 + k0 + 2 * tig);
                    al[mt][1] = *(const uint32_t*)(Xl + r8 + k0 + 2 * tig);
                    al[mt][2] = *(const uint32_t*)(Xl + r0 + k0 + 2 * tig + 8);
                    al[mt][3] = *(const uint32_t*)(Xl + r8 + k0 + 2 * tig + 8);
                }
                const int kk = p * 64 + k0;
                uint32_t bh[4][2], bl[4][2];
                #pragma unroll
                for (int nt = 0; nt < 4; ++nt) {
                    int n = (wn + nt * 8 + gid) * WS;
                    bh[nt][0] = *(const uint32_t*)(W1h + n + kk + 2 * tig);
                    bh[nt][1] = *(const uint32_t*)(W1h + n + kk + 2 * tig + 8);
                    bl[nt][0] = *(const uint32_t*)(W1l + n + kk + 2 * tig);
                    bl[nt][1] = *(const uint32_t*)(W1l + n + kk + 2 * tig + 8);
                }
                #pragma unroll
                for (int nt = 0; nt < 4; ++nt) {
                    mma_16816(acc[0][nt], ah[0], bh[nt]);
                    mma_16816(acc[1][nt], ah[1], bh[nt]);
                }
                #pragma unroll
                for (int nt = 0; nt < 4; ++nt) {
                    mma_16816(acc[0][nt], ah[0], bl[nt]);
                    mma_16816(acc[1][nt], ah[1], bl[nt]);
                }
                #pragma unroll
                for (int nt = 0; nt < 4; ++nt) {
                    mma_16816(acc[0][nt], al[0], bh[nt]);
                    mma_16816(acc[1][nt], al[1], bh[nt]);
                }
            }
        }

        #pragma unroll
        for (int mt = 0; mt < 2; ++mt)
            #pragma unroll
            for (int nt = 0; nt < 4; ++nt) {
                int r0 = wm + mt * 16 + gid;
                int c0 = wn + nt * 8 + 2 * tig;
                float v0 = fmaxf(acc[mt][nt][0], 0.f);
                float v1 = fmaxf(acc[mt][nt][1], 0.f);
                float v2 = fmaxf(acc[mt][nt][2], 0.f);
                float v3 = fmaxf(acc[mt][nt][3], 0.f);
                __half2 hi, lo;
                split2(v0, v1, hi, lo);
                *(__half2*)(Hh + r0 * XS + c0) = hi;
                *(__half2*)(Hl + r0 * XS + c0) = lo;
                split2(v2, v3, hi, lo);
                *(__half2*)(Hh + (r0 + 8) * XS + c0) = hi;
                *(__half2*)(Hl + (r0 + 8) * XS + c0) = lo;
            }
        __syncthreads();

        float o[2][4][4];
        #pragma unroll
        for (int nt = 0; nt < 4; ++nt) {
            float bv0 = b2s[wn + nt * 8 + 2 * tig];
            float bv1 = b2s[wn + nt * 8 + 2 * tig + 1];
            #pragma unroll
            for (int mt = 0; mt < 2; ++mt) {
                o[mt][nt][0] = bv0; o[mt][nt][1] = bv1;
                o[mt][nt][2] = bv0; o[mt][nt][3] = bv1;
            }
        }
        #pragma unroll
        for (int kb = 0; kb < 4; ++kb) {
            const int k0 = kb * 16;
            uint32_t ah[2][4], al[2][4];
            #pragma unroll
            for (int mt = 0; mt < 2; ++mt) {
                int r0 = (wm + mt * 16 + gid) * XS;
                int r8 = r0 + 8 * XS;
                ah[mt][0] = *(const uint32_t*)(Hh + r0 + k0 + 2 * tig);
                ah[mt][1] = *(const uint32_t*)(Hh + r8 + k0 + 2 * tig);
                ah[mt][2] = *(const uint32_t*)(Hh + r0 + k0 + 2 * tig + 8);
                ah[mt][3] = *(const uint32_t*)(Hh + r8 + k0 + 2 * tig + 8);
                al[mt][0] = *(const uint32_t*)(Hl + r0 + k0 + 2 * tig);
                al[mt][1] = *(const uint32_t*)(Hl + r8 + k0 + 2 * tig);
                al[mt][2] = *(const uint32_t*)(Hl + r0 + k0 + 2 * tig + 8);
                al[mt][3] = *(const uint32_t*)(Hl + r8 + k0 + 2 * tig + 8);
            }
            uint32_t bh[4][2], bl[4][2];
            #pragma unroll
            for (int nt = 0; nt < 4; ++nt) {
                int n = (wn + nt * 8 + gid) * XS;
                bh[nt][0] = *(const uint32_t*)(W2h + n + k0 + 2 * tig);
                bh[nt][1] = *(const uint32_t*)(W2h + n + k0 + 2 * tig + 8);
                bl[nt][0] = *(const uint32_t*)(W2l + n + k0 + 2 * tig);
                bl[nt][1] = *(const uint32_t*)(W2l + n + k0 + 2 * tig + 8);
            }
            #pragma unroll
            for (int nt = 0; nt < 4; ++nt) {
                mma_16816(o[0][nt], ah[0], bh[nt]);
                mma_16816(o[1][nt], ah[1], bh[nt]);
            }
            #pragma unroll
            for (int nt = 0; nt < 4; ++nt) {
                mma_16816(o[0][nt], ah[0], bl[nt]);
                mma_16816(o[1][nt], ah[1], bl[nt]);
            }
            #pragma unroll
            for (int nt = 0; nt < 4; ++nt) {
                mma_16816(o[0][nt], al[0], bh[nt]);
                mma_16816(o[1][nt], al[1], bh[nt]);
            }
        }

        #pragma unroll
        for (int mt = 0; mt < 2; ++mt)
            #pragma unroll
            for (int nt = 0; nt < 4; ++nt) {
                int r = base + wm + mt * 16 + gid;
                int c = wn + nt * 8 + 2 * tig;
                if (r < nrows) {
                    int ro = FLIPOUT ? (r ^ 1) : r;
                    *(float2*)(out + (size_t)ro * 64 + c) =
                        make_float2(o[mt][nt][0], o[mt][nt][1]);
                }
                if (r + 8 < nrows) {
                    int ro = FLIPOUT ? ((r + 8) ^ 1) : (r + 8);
                    *(float2*)(out + (size_t)ro * 64 + c) =
                        make_float2(o[mt][nt][2], o[mt][nt][3]);
                }
            }
    }
}

// ---------------------------------------------------------------------------
// CSR build: count -> 3-kernel exclusive scan -> atomic placement
// ---------------------------------------------------------------------------
__global__ void count_kernel(const int* __restrict__ dest, int E, int* __restrict__ cnt)
{
    int e = blockIdx.x * 256 + threadIdx.x;
    if (e < E) atomicAdd(&cnt[dest[e]], 1);
}

__global__ void scan_reduce(const int* __restrict__ cnt, int n, int* __restrict__ bsum)
{
    int b = blockIdx.x;
    int CH = (n + SCAN_NB - 1) / SCAN_NB;
    int s = b * CH, e = min(n, s + CH);
    __shared__ int sh[256];
    int t = threadIdx.x, sum = 0;
    for (int i = s + t; i < e; i += 256) sum += cnt[i];
    sh[t] = sum; __syncthreads();
    for (int o = 128; o > 0; o >>= 1) {
        if (t < o) sh[t] += sh[t + o];
        __syncthreads();
    }
    if (t == 0) bsum[b] = sh[0];
}

__global__ void scan_bsum(int* __restrict__ bsum)
{
    __shared__ int sh[256];
    int t = threadIdx.x;
    sh[t] = bsum[t]; __syncthreads();
    for (int o = 1; o < 256; o <<= 1) {
        int v = (t >= o) ? sh[t - o] : 0;
        __syncthreads();
        sh[t] += v;
        __syncthreads();
    }
    bsum[t] = (t == 0) ? 0 : sh[t - 1];
}

__global__ void scan_write(const int* __restrict__ cnt, int n,
                           const int* __restrict__ bsum, int* __restrict__ rowptr, int total)
{
    int b = blockIdx.x;
    int CH = (n + SCAN_NB - 1) / SCAN_NB;
    int s = b * CH, e = min(n, s + CH);
    int t = threadIdx.x;
    int per = (CH + 255) / 256;
    int ts = min(e, s + t * per), te = min(e, s + t * per + per);
    int sum = 0;
    for (int i = ts; i < te; ++i) sum += cnt[i];
    __shared__ int sh[256];
    sh[t] = sum; __syncthreads();
    for (int o = 1; o < 256; o <<= 1) {
        int v = (t >= o) ? sh[t - o] : 0;
        __syncthreads();
        sh[t] += v;
        __syncthreads();
    }
    int off = bsum[b] + ((t == 0) ? 0 : sh[t - 1]);
    for (int i = ts; i < te; ++i) { rowptr[i] = off; off += cnt[i]; }
    if (b == 0 && t == 0) rowptr[n] = total;
}

__global__ void place_kernel(const int* __restrict__ dest, const int* __restrict__ srcn,
                             int E, int* __restrict__ cursor, int* __restrict__ srcidx)
{
    int e = blockIdx.x * 256 + threadIdx.x;
    if (e < E) {
        int p = atomicAdd(&cursor[dest[e]], 1);
        srcidx[p] = srcn[e];
    }
}

// ---------------------------------------------------------------------------
// Gather aggregation: dst[d] = sum over CSR row d of src[srcidx[i]]  (64 floats)
// Half-warp (16 lanes) per destination; each lane owns one float4 column.
// ---------------------------------------------------------------------------
__global__ __launch_bounds__(256) void gather_kernel(
    const float* __restrict__ src, const int* __restrict__ srcidx,
    const int* __restrict__ rowptr, float* __restrict__ dst, int n)
{
    int d = blockIdx.x * 16 + (threadIdx.x >> 4);
    int q = threadIdx.x & 15;
    if (d >= n) return;
    int s = rowptr[d], e = rowptr[d + 1];
    float ax = 0.f, ay = 0.f, az = 0.f, aw = 0.f;
    for (int i = s; i < e; ++i) {
        int r = __ldg(srcidx + i);
        float4 v = *(const float4*)(src + (size_t)r * 64 + q * 4);
        ax += v.x; ay += v.y; az += v.z; aw += v.w;
    }
    *(float4*)(dst + (size_t)d * 64 + q * 4) = make_float4(ax, ay, az, aw);
}

// ---------------------------------------------------------------------------
static inline size_t mlp_smem_bytes(int parts)
{
    int WS = parts * 64 + 8;
    size_t halves = (size_t)2 * 64 * WS + (size_t)6 * 64 * 72;
    return halves * 2 + 128 * sizeof(float);
}

extern "C" void kernel_launch(void* const* d_in, const int* in_sizes, int n_in,
                              void* d_out, int out_size)
{
    const int off = n_in - 24;
    const int* l_edge = (const int*)d_in[off + 0];
    const int* c_edge = (const int*)d_in[off + 1];
    const float* l_emb_in = (const float*)d_in[off + 2];
    const float* c_emb_in = (const float*)d_in[off + 3];
    const int E = in_sizes[off + 0];
    const int L = in_sizes[off + 2] / DIM;
    const int C = in_sizes[off + 3] / DIM;

    const float* W[5][4];
    for (int m = 0; m < 5; ++m)
        for (int j = 0; j < 4; ++j)
            W[m][j] = (const float*)d_in[off + 4 + m * 4 + j];

    float* Ml2c, * Mc2l, * Ml2l, * aggrC, * aggrL;
    int *cntC, *rowC, *curC, *srcC, *bsC;
    int *cntL, *rowL, *curL, *srcL, *bsL;
    cudaGetSymbolAddress((void**)&Ml2c, g_Ml2c);
    cudaGetSymbolAddress((void**)&Mc2l, g_Mc2l);
    cudaGetSymbolAddress((void**)&Ml2l, g_Ml2l);
    cudaGetSymbolAddress((void**)&aggrC, g_aggrC);
    cudaGetSymbolAddress((void**)&aggrL, g_aggrL);
    cudaGetSymbolAddress((void**)&cntC, g_cntC);
    cudaGetSymbolAddress((void**)&rowC, g_rowC);
    cudaGetSymbolAddress((void**)&curC, g_curC);
    cudaGetSymbolAddress((void**)&srcC, g_srcC);
    cudaGetSymbolAddress((void**)&bsC,  g_bsumC);
    cudaGetSymbolAddress((void**)&cntL, g_cntL);
    cudaGetSymbolAddress((void**)&rowL, g_rowL);
    cudaGetSymbolAddress((void**)&curL, g_curL);
    cudaGetSymbolAddress((void**)&srcL, g_srcL);
    cudaGetSymbolAddress((void**)&bsL,  g_bsumL);

    const size_t sm1 = mlp_smem_bytes(1);
    const size_t sm2 = mlp_smem_bytes(2);
    const size_t sm3 = mlp_smem_bytes(3);
    cudaFuncSetAttribute(mlp_tc<1, false>, cudaFuncAttributeMaxDynamicSharedMemorySize, (int)sm1);
    cudaFuncSetAttribute(mlp_tc<1, true>,  cudaFuncAttributeMaxDynamicSharedMemorySize, (int)sm1);
    cudaFuncSetAttribute(mlp_tc<2, false>, cudaFuncAttributeMaxDynamicSharedMemorySize, (int)sm2);
    cudaFuncSetAttribute(mlp_tc<3, false>, cudaFuncAttributeMaxDynamicSharedMemorySize, (int)sm3);

    float* outBase = (float*)d_out;
    float* outL = outBase;                          // (3, L, 64)
    float* outC = outBase + (size_t)3 * L * DIM;    // (3, C, 64)

    cudaMemcpyAsync(outL, l_emb_in, (size_t)L * DIM * sizeof(float), cudaMemcpyDeviceToDevice);
    cudaMemcpyAsync(outC, c_emb_in, (size_t)C * DIM * sizeof(float), cudaMemcpyDeviceToDevice);

    // ---- CSR build (edges are iteration-invariant; amortized over 4 gathers) ----
    const int eb = (E + 255) / 256;
    // clause CSR: dest = c_edge, store src = l_edge
    cudaMemsetAsync(cntC, 0, C * sizeof(int));
    count_kernel<<<eb, 256>>>(c_edge, E, cntC);
    scan_reduce<<<SCAN_NB, 256>>>(cntC, C, bsC);
    scan_bsum<<<1, 256>>>(bsC);
    scan_write<<<SCAN_NB, 256>>>(cntC, C, bsC, rowC, E);
    cudaMemcpyAsync(curC, rowC, C * sizeof(int), cudaMemcpyDeviceToDevice);
    place_kernel<<<eb, 256>>>(c_edge, l_edge, E, curC, srcC);
    // literal CSR: dest = l_edge, store src = c_edge
    cudaMemsetAsync(cntL, 0, L * sizeof(int));
    count_kernel<<<eb, 256>>>(l_edge, E, cntL);
    scan_reduce<<<SCAN_NB, 256>>>(cntL, L, bsL);
    scan_bsum<<<1, 256>>>(bsL);
    scan_write<<<SCAN_NB, 256>>>(cntL, L, bsL, rowL, E);
    cudaMemcpyAsync(curL, rowL, L * sizeof(int), cudaMemcpyDeviceToDevice);
    place_kernel<<<eb, 256>>>(l_edge, c_edge, E, curL, srcL);

    const int ltiles = (L + 63) >> 6;
    const int ctiles = (C + 63) >> 6;
    auto gridFor = [](int tiles, int maxResident) {
        return tiles < maxResident ? tiles : maxResident;
    };
    const int g1L = gridFor(ltiles, 148 * 3);
    const int g1C = gridFor(ctiles, 148 * 3);
    const int g2C = gridFor(ctiles, 148 * 2);
    const int g3L = gridFor(ltiles, 148 * 2);

    for (int t = 0; t < 2; ++t) {
        const float* le = outL + (size_t)t * L * DIM;
        const float* ce = outC + (size_t)t * C * DIM;
        float* nle = outL + (size_t)(t + 1) * L * DIM;
        float* nce = outC + (size_t)(t + 1) * C * DIM;

        // messages (from OLD embeddings)
        mlp_tc<1, false><<<g1L, 128, sm1>>>(le, nullptr, nullptr,
            W[0][0], W[0][1], W[0][2], W[0][3], Ml2c, L);
        mlp_tc<1, false><<<g1C, 128, sm1>>>(ce, nullptr, nullptr,
            W[1][0], W[1][1], W[1][2], W[1][3], Mc2l, C);
        mlp_tc<1, true><<<g1L, 128, sm1>>>(le, nullptr, nullptr,
            W[2][0], W[2][1], W[2][2], W[2][3], Ml2l, L);

        // aggregation via gather (no atomics, no memsets)
        gather_kernel<<<(C + 15) / 16, 256>>>(Ml2c, srcC, rowC, aggrC, C);
        gather_kernel<<<(L + 15) / 16, 256>>>(Mc2l, srcL, rowL, aggrL, L);

        // updates
        mlp_tc<2, false><<<g2C, 128, sm2>>>(ce, aggrC, nullptr,
            W[3][0], W[3][1], W[3][2], W[3][3], nce, C);
        mlp_tc<3, false><<<g3L, 128, sm3>>>(le, aggrL, Ml2l,
            W[4][0], W[4][1], W[4][2], W[4][3], nle, L);
    }
    (void)out_size;
}